// round 1
// baseline (speedup 1.0000x reference)
#include <cuda_runtime.h>
#include <math.h>

#define Bb 4
#define Tt 2048
#define Dm 1024
#define Ee 6
#define Pp 36
#define DAa 512
#define NCHUNK 32
#define RPC (Tt / NCHUNK) // 64 rows per chunk
#define THRESH 0.3f
#define LN_EPS 1e-5f
#define OUT_MAIN (Bb * Tt * Dm) // 8388608

// ---------------- scratch (static device globals; no allocation) -------------
__device__ float g_u[Ee * Dm];
__device__ float g_pm[Ee * Bb * NCHUNK];
__device__ float g_ps[Ee * Bb * NCHUNK];
__device__ float g_pacc[Ee * Bb * NCHUNK * Dm]; // 3 MB
__device__ float g_y[Ee * Bb * Dm];
__device__ float g_form[Ee * Bb * Dm];
__device__ float g_c[Pp * Bb * 2 * DAa];
__device__ float g_hpre[Pp * Bb * DAa];
__device__ float g_hs[Pp * Bb * Dm];
__device__ float g_strength[Pp * Bb];
__device__ float g_avg[Pp];
__device__ float g_scalepb[Pp * Bb]; // mask * pair_gate * strength
__device__ float g_count;
__device__ float g_total[Bb * Dm];
__device__ float g_normed[Bb * Dm];
__device__ float g_addition[Bb * Dm];

__device__ __forceinline__ float gelu_exact(float x) {
    return 0.5f * x * (1.0f + erff(x * 0.70710678118654752f));
}

// ---------------- init accumulators with biases ------------------------------
__global__ void k_init(const float* __restrict__ bv, const float* __restrict__ ba,
                       const float* __restrict__ bb, const float* __restrict__ gb1,
                       const float* __restrict__ sb1) {
    int i = blockIdx.x * blockDim.x + threadIdx.x;
    if (i < Ee * Bb * Dm) {
        int e = i / (Bb * Dm);
        int f = i % Dm;
        g_form[i] = bv[e * Dm + f];
        return;
    }
    i -= Ee * Bb * Dm;
    if (i < Pp * Bb * 1024) {
        int p = i / (Bb * 1024);
        int j = i % 1024;
        g_c[i] = (j < DAa) ? ba[p * DAa + j] : bb[p * DAa + (j - DAa)];
        return;
    }
    i -= Pp * Bb * 1024;
    if (i < Pp * Bb * DAa) {
        int p = i / (Bb * DAa);
        int a = i % DAa;
        g_hpre[i] = gb1[p * DAa + a];
        return;
    }
    i -= Pp * Bb * DAa;
    if (i < Pp * Bb * Dm) {
        int p = i / (Bb * Dm);
        int d = i % Dm;
        g_hs[i] = sb1[p * Dm + d];
        return;
    }
    i -= Pp * Bb * Dm;
    if (i < Bb * Dm) g_total[i] = 0.0f;
}

// ---------------- u[e,d] = scale * sum_f Wk[e,d,f] * q[e,f] ------------------
__global__ void k_u(const float* __restrict__ Wk, const float* __restrict__ q) {
    int warp = (blockIdx.x * blockDim.x + threadIdx.x) >> 5;
    int lane = threadIdx.x & 31;
    if (warp >= Ee * Dm) return;
    int e = warp / Dm, d = warp % Dm;
    const float4* w4 = reinterpret_cast<const float4*>(Wk + ((size_t)e * Dm + d) * Dm);
    const float4* q4 = reinterpret_cast<const float4*>(q + e * Dm);
    float s = 0.0f;
#pragma unroll
    for (int f = lane; f < Dm / 4; f += 32) {
        float4 a = w4[f], b = q4[f];
        s += a.x * b.x + a.y * b.y + a.z * b.z + a.w * b.w;
    }
#pragma unroll
    for (int o = 16; o; o >>= 1) s += __shfl_down_sync(0xffffffffu, s, o);
    if (!lane) g_u[warp] = s * 0.03125f; // D^-0.5 = 1/32
}

// ---------------- fused condenser: one pass, online softmax ------------------
__global__ void __launch_bounds__(256) k_condense(const float* __restrict__ eo,
                                                  const float* __restrict__ ew) {
    int bid = blockIdx.x;
    int chunk = bid % NCHUNK;
    int eb = bid / NCHUNK;
    int e = eb / Bb, b = eb % Bb;
    int tid = threadIdx.x;
    __shared__ float s_red[8];
    __shared__ float s_dot;
    __shared__ float s_w[RPC];
    if (tid < RPC) {
        int t = chunk * RPC + tid;
        s_w[tid] = ew[((size_t)b * Tt + t) * Ee + e];
    }
    float4 uv = reinterpret_cast<const float4*>(g_u + e * Dm)[tid];
    const float4* xbase = reinterpret_cast<const float4*>(
        eo + (((size_t)e * Bb + b) * Tt + (size_t)chunk * RPC) * Dm);
    __syncthreads();

    float m = -1e30f, ssum = 0.0f;
    float4 acc = {0.f, 0.f, 0.f, 0.f};
    float4 xv = xbase[tid]; // prefetch row 0
    for (int r = 0; r < RPC; ++r) {
        float4 cur = xv;
        if (r + 1 < RPC) xv = xbase[(size_t)(r + 1) * 256 + tid]; // prefetch next
        float pd = cur.x * uv.x + cur.y * uv.y + cur.z * uv.z + cur.w * uv.w;
#pragma unroll
        for (int o = 16; o; o >>= 1) pd += __shfl_down_sync(0xffffffffu, pd, o);
        if ((tid & 31) == 0) s_red[tid >> 5] = pd;
        __syncthreads();
        if (tid == 0) {
            s_dot = s_red[0] + s_red[1] + s_red[2] + s_red[3] +
                    s_red[4] + s_red[5] + s_red[6] + s_red[7];
        }
        __syncthreads();
        float w = s_w[r];
        float l = s_dot * w;
        if (l > m) {
            float f = __expf(m - l);
            acc.x *= f; acc.y *= f; acc.z *= f; acc.w *= f;
            ssum *= f;
            m = l;
        }
        float pe = __expf(l - m);
        ssum += pe;
        float cf = pe * w;
        acc.x += cf * cur.x; acc.y += cf * cur.y;
        acc.z += cf * cur.z; acc.w += cf * cur.w;
    }
    if (tid == 0) {
        g_pm[bid] = m;
        g_ps[bid] = ssum;
    }
    reinterpret_cast<float4*>(g_pacc + (size_t)bid * Dm)[tid] = acc;
}

// ---------------- combine split-softmax partials -> y ------------------------
__global__ void k_combine() {
    int eb = blockIdx.x;
    int tid = threadIdx.x;
    float M = -1e30f;
#pragma unroll
    for (int c = 0; c < NCHUNK; c++) M = fmaxf(M, g_pm[eb * NCHUNK + c]);
    float S = 0.0f;
    float4 y = {0.f, 0.f, 0.f, 0.f};
    for (int c = 0; c < NCHUNK; c++) {
        int pidx = eb * NCHUNK + c;
        float f = __expf(g_pm[pidx] - M);
        S += g_ps[pidx] * f;
        float4 a = reinterpret_cast<const float4*>(g_pacc + (size_t)pidx * Dm)[tid];
        y.x += a.x * f; y.y += a.y * f; y.z += a.z * f; y.w += a.w * f;
    }
    float inv = 1.0f / S;
    y.x *= inv; y.y *= inv; y.z *= inv; y.w *= inv;
    reinterpret_cast<float4*>(g_y + (size_t)eb * Dm)[tid] = y;
}

// ---------------- formulas = y @ Wv (+bv already in g_form) ------------------
__global__ void __launch_bounds__(256) k_form(const float* __restrict__ Wv) {
    int e = blockIdx.x >> 3, ds = blockIdx.x & 7;
    int tid = threadIdx.x;
    __shared__ float s_in[Bb * Dm];
#pragma unroll
    for (int k = tid; k < Bb * Dm / 4; k += 256)
        reinterpret_cast<float4*>(s_in)[k] =
            reinterpret_cast<const float4*>(g_y + (size_t)e * Bb * Dm)[k];
    __syncthreads();
    const float* Wp = Wv + (size_t)e * Dm * Dm;
    float4 acc[Bb] = {};
    int d0 = ds * 128;
#pragma unroll 4
    for (int d = d0; d < d0 + 128; ++d) {
        float4 wv = reinterpret_cast<const float4*>(Wp + (size_t)d * Dm)[tid];
#pragma unroll
        for (int b = 0; b < Bb; b++) {
            float x = s_in[b * Dm + d];
            acc[b].x += x * wv.x; acc[b].y += x * wv.y;
            acc[b].z += x * wv.z; acc[b].w += x * wv.w;
        }
    }
#pragma unroll
    for (int b = 0; b < Bb; b++) {
        float* dst = g_form + ((size_t)e * Bb + b) * Dm + 4 * tid;
        atomicAdd(dst + 0, acc[b].x); atomicAdd(dst + 1, acc[b].y);
        atomicAdd(dst + 2, acc[b].z); atomicAdd(dst + 3, acc[b].w);
    }
}

// ---------------- pair a/b projections: c[p] = [fa@Wa | fb@Wb] ---------------
__global__ void __launch_bounds__(128) k_pair_ab(const float* __restrict__ Wa,
                                                 const float* __restrict__ Wb) {
    int bid = blockIdx.x;
    int ds = bid & 3;
    int half = (bid >> 2) & 1;
    int p = bid >> 3;
    int src = half ? (p % Ee) : (p / Ee); // PJ : PI
    const float* Wp = (half ? Wb : Wa) + (size_t)p * Dm * DAa;
    int tid = threadIdx.x;
    __shared__ float s_in[Bb * Dm];
#pragma unroll
    for (int k = tid; k < Bb * Dm / 4; k += 128)
        reinterpret_cast<float4*>(s_in)[k] =
            reinterpret_cast<const float4*>(g_form + (size_t)src * Bb * Dm)[k];
    __syncthreads();
    float4 acc[Bb] = {};
    int d0 = ds * 256;
#pragma unroll 4
    for (int d = d0; d < d0 + 256; ++d) {
        float4 wv = reinterpret_cast<const float4*>(Wp + (size_t)d * DAa)[tid];
#pragma unroll
        for (int b = 0; b < Bb; b++) {
            float x = s_in[b * Dm + d];
            acc[b].x += x * wv.x; acc[b].y += x * wv.y;
            acc[b].z += x * wv.z; acc[b].w += x * wv.w;
        }
    }
#pragma unroll
    for (int b = 0; b < Bb; b++) {
        float* dst = g_c + ((size_t)p * Bb + b) * 1024 + half * DAa + 4 * tid;
        atomicAdd(dst + 0, acc[b].x); atomicAdd(dst + 1, acc[b].y);
        atomicAdd(dst + 2, acc[b].z); atomicAdd(dst + 3, acc[b].w);
    }
}

// ---------------- gate pre-activation: hpre = c @ gate_W1 --------------------
__global__ void __launch_bounds__(128) k_gate1(const float* __restrict__ gW1) {
    int bid = blockIdx.x;
    int ds = bid & 3;
    int p = bid >> 2;
    int tid = threadIdx.x;
    __shared__ float s_in[Bb * 1024];
#pragma unroll
    for (int k = tid; k < Bb * 1024 / 4; k += 128)
        reinterpret_cast<float4*>(s_in)[k] =
            reinterpret_cast<const float4*>(g_c + (size_t)p * Bb * 1024)[k];
    __syncthreads();
    const float* Wp = gW1 + (size_t)p * 1024 * DAa;
    float4 acc[Bb] = {};
    int d0 = ds * 256;
#pragma unroll 4
    for (int d = d0; d < d0 + 256; ++d) {
        float4 wv = reinterpret_cast<const float4*>(Wp + (size_t)d * DAa)[tid];
#pragma unroll
        for (int b = 0; b < Bb; b++) {
            float x = s_in[b * 1024 + d];
            acc[b].x += x * wv.x; acc[b].y += x * wv.y;
            acc[b].z += x * wv.z; acc[b].w += x * wv.w;
        }
    }
#pragma unroll
    for (int b = 0; b < Bb; b++) {
        float* dst = g_hpre + ((size_t)p * Bb + b) * DAa + 4 * tid;
        atomicAdd(dst + 0, acc[b].x); atomicAdd(dst + 1, acc[b].y);
        atomicAdd(dst + 2, acc[b].z); atomicAdd(dst + 3, acc[b].w);
    }
}

// ---------------- syn hidden pre-activation: g_hs += c @ syn_W1 --------------
__global__ void __launch_bounds__(256) k_syn1(const float* __restrict__ sW1) {
    int bid = blockIdx.x;
    int ds = bid & 7;
    int p = bid >> 3;
    int tid = threadIdx.x;
    __shared__ float s_in[Bb * 1024];
#pragma unroll
    for (int k = tid; k < Bb * 1024 / 4; k += 256)
        reinterpret_cast<float4*>(s_in)[k] =
            reinterpret_cast<const float4*>(g_c + (size_t)p * Bb * 1024)[k];
    __syncthreads();
    const float* Wp = sW1 + (size_t)p * 1024 * Dm;
    float4 acc[Bb] = {};
    int d0 = ds * 128;
#pragma unroll 4
    for (int d = d0; d < d0 + 128; ++d) {
        float4 wv = reinterpret_cast<const float4*>(Wp + (size_t)d * Dm)[tid];
#pragma unroll
        for (int b = 0; b < Bb; b++) {
            float x = s_in[b * 1024 + d];
            acc[b].x += x * wv.x; acc[b].y += x * wv.y;
            acc[b].z += x * wv.z; acc[b].w += x * wv.w;
        }
    }
#pragma unroll
    for (int b = 0; b < Bb; b++) {
        float* dst = g_hs + ((size_t)p * Bb + b) * Dm + 4 * tid;
        atomicAdd(dst + 0, acc[b].x); atomicAdd(dst + 1, acc[b].y);
        atomicAdd(dst + 2, acc[b].z); atomicAdd(dst + 3, acc[b].w);
    }
}

// ---------------- gelu in place on g_hs ---------------------------------------
__global__ void k_act_hs() {
    int i = blockIdx.x * blockDim.x + threadIdx.x;
    if (i < Pp * Bb * Dm) g_hs[i] = gelu_exact(g_hs[i]);
}

// ---------------- strength = sigmoid(gelu(hpre) @ gate_W2 + b2) --------------
__global__ void __launch_bounds__(128) k_strength(const float* __restrict__ gW2,
                                                  const float* __restrict__ gb2,
                                                  const float* __restrict__ pg) {
    int p = blockIdx.x, tid = threadIdx.x;
    float part[Bb] = {0.f, 0.f, 0.f, 0.f};
    for (int a = tid; a < DAa; a += 128) {
        float w2 = gW2[p * DAa + a];
#pragma unroll
        for (int b = 0; b < Bb; b++) {
            float h = g_hpre[((size_t)p * Bb + b) * DAa + a];
            part[b] += gelu_exact(h) * w2;
        }
    }
    __shared__ float s_red[Bb][4];
#pragma unroll
    for (int b = 0; b < Bb; b++) {
        float v = part[b];
#pragma unroll
        for (int o = 16; o; o >>= 1) v += __shfl_down_sync(0xffffffffu, v, o);
        if ((tid & 31) == 0) s_red[b][tid >> 5] = v;
    }
    __syncthreads();
    if (tid == 0) {
        float avg = 0.0f;
        float st[Bb];
#pragma unroll
        for (int b = 0; b < Bb; b++) {
            float d = s_red[b][0] + s_red[b][1] + s_red[b][2] + s_red[b][3] + gb2[p];
            st[b] = 1.0f / (1.0f + expf(-d));
            avg += st[b];
        }
        avg *= 0.25f;
        g_avg[p] = avg;
        float mk = (avg > THRESH) ? pg[p] : 0.0f;
#pragma unroll
        for (int b = 0; b < Bb; b++) {
            g_strength[p * Bb + b] = st[b];
            g_scalepb[p * Bb + b] = mk * st[b];
        }
    }
}

// ---------------- count actives; write aux outputs ----------------------------
__global__ void k_count(float* __restrict__ out, int out_size) {
    if (threadIdx.x == 0) {
        float c = 0.0f;
        for (int p = 0; p < Pp; p++) c += (g_avg[p] > THRESH) ? 1.0f : 0.0f;
        g_count = c;
        if (out_size >= OUT_MAIN + Pp + 1) out[OUT_MAIN + Pp] = c;
    }
    if (threadIdx.x < Pp && out_size >= OUT_MAIN + Pp + 1)
        out[OUT_MAIN + threadIdx.x] = g_avg[threadIdx.x];
}

// ---------------- total bias term: sum_p scale_pb * syn_b2 -------------------
__global__ void k_biastotal(const float* __restrict__ sb2) {
    int i = blockIdx.x * blockDim.x + threadIdx.x;
    if (i >= Bb * Dm) return;
    int b = i >> 10;
    int j = i & 1023;
    float s = 0.0f;
#pragma unroll
    for (int p = 0; p < Pp; p++) s += g_scalepb[p * Bb + b] * sb2[p * Dm + j];
    g_total[i] = s;
}

// ---------------- total += scale_pb * (hs @ syn_W2) ---------------------------
__global__ void __launch_bounds__(256) k_syn2(const float* __restrict__ sW2) {
    int bid = blockIdx.x;
    int ds = bid & 7;
    int p = bid >> 3;
    int tid = threadIdx.x;
    __shared__ float s_in[Bb * Dm];
#pragma unroll
    for (int k = tid; k < Bb * Dm / 4; k += 256)
        reinterpret_cast<float4*>(s_in)[k] =
            reinterpret_cast<const float4*>(g_hs + (size_t)p * Bb * Dm)[k];
    __syncthreads();
    const float* Wp = sW2 + (size_t)p * Dm * Dm;
    float4 acc[Bb] = {};
    int d0 = ds * 128;
#pragma unroll 4
    for (int d = d0; d < d0 + 128; ++d) {
        float4 wv = reinterpret_cast<const float4*>(Wp + (size_t)d * Dm)[tid];
#pragma unroll
        for (int b = 0; b < Bb; b++) {
            float x = s_in[b * Dm + d];
            acc[b].x += x * wv.x; acc[b].y += x * wv.y;
            acc[b].z += x * wv.z; acc[b].w += x * wv.w;
        }
    }
#pragma unroll
    for (int b = 0; b < Bb; b++) {
        float sc = g_scalepb[p * Bb + b];
        float* dst = g_total + b * Dm + 4 * tid;
        atomicAdd(dst + 0, acc[b].x * sc); atomicAdd(dst + 1, acc[b].y * sc);
        atomicAdd(dst + 2, acc[b].z * sc); atomicAdd(dst + 3, acc[b].w * sc);
    }
}

// ---------------- LayerNorm(total / max(count,1)) -----------------------------
__global__ void __launch_bounds__(256) k_ln(const float* __restrict__ gamma,
                                            const float* __restrict__ beta,
                                            const float* __restrict__ out_b,
                                            const float* __restrict__ ag_p) {
    int tid = threadIdx.x;
    __shared__ float s_red[8];
    __shared__ float s_stat;
    float inv_cnt = 1.0f / fmaxf(g_count, 1.0f);
    float ag = *ag_p;
    float4 ga = reinterpret_cast<const float4*>(gamma)[tid];
    float4 be = reinterpret_cast<const float4*>(beta)[tid];
    for (int b = 0; b < Bb; b++) {
        float4 v = reinterpret_cast<const float4*>(g_total + b * Dm)[tid];
        v.x *= inv_cnt; v.y *= inv_cnt; v.z *= inv_cnt; v.w *= inv_cnt;
        // mean
        float lsum = v.x + v.y + v.z + v.w;
#pragma unroll
        for (int o = 16; o; o >>= 1) lsum += __shfl_down_sync(0xffffffffu, lsum, o);
        if ((tid & 31) == 0) s_red[tid >> 5] = lsum;
        __syncthreads();
        if (tid == 0) {
            float t = 0;
#pragma unroll
            for (int k = 0; k < 8; k++) t += s_red[k];
            s_stat = t * (1.0f / Dm);
        }
        __syncthreads();
        float mu = s_stat;
        __syncthreads();
        float dx = v.x - mu, dy = v.y - mu, dz = v.z - mu, dw = v.w - mu;
        float lsq = dx * dx + dy * dy + dz * dz + dw * dw;
#pragma unroll
        for (int o = 16; o; o >>= 1) lsq += __shfl_down_sync(0xffffffffu, lsq, o);
        if ((tid & 31) == 0) s_red[tid >> 5] = lsq;
        __syncthreads();
        if (tid == 0) {
            float t = 0;
#pragma unroll
            for (int k = 0; k < 8; k++) t += s_red[k];
            s_stat = t * (1.0f / Dm);
        }
        __syncthreads();
        float rstd = rsqrtf(s_stat + LN_EPS);
        __syncthreads();
        float4 nv;
        nv.x = dx * rstd * ga.x + be.x;
        nv.y = dy * rstd * ga.y + be.y;
        nv.z = dz * rstd * ga.z + be.z;
        nv.w = dw * rstd * ga.w + be.w;
        reinterpret_cast<float4*>(g_normed + b * Dm)[tid] = nv;
    }
    // init addition with (out_b * gate)
    float4 ob = reinterpret_cast<const float4*>(out_b)[tid];
    ob.x *= ag; ob.y *= ag; ob.z *= ag; ob.w *= ag;
#pragma unroll
    for (int b = 0; b < Bb; b++)
        reinterpret_cast<float4*>(g_addition + b * Dm)[tid] = ob;
}

// ---------------- addition += (normed @ out_W) * gate -------------------------
__global__ void __launch_bounds__(256) k_proj(const float* __restrict__ out_W,
                                              const float* __restrict__ ag_p) {
    int ds = blockIdx.x;
    int tid = threadIdx.x;
    __shared__ float s_in[Bb * Dm];
#pragma unroll
    for (int k = tid; k < Bb * Dm / 4; k += 256)
        reinterpret_cast<float4*>(s_in)[k] = reinterpret_cast<const float4*>(g_normed)[k];
    __syncthreads();
    float4 acc[Bb] = {};
    int d0 = ds * 128;
#pragma unroll 4
    for (int d = d0; d < d0 + 128; ++d) {
        float4 wv = reinterpret_cast<const float4*>(out_W + (size_t)d * Dm)[tid];
#pragma unroll
        for (int b = 0; b < Bb; b++) {
            float x = s_in[b * Dm + d];
            acc[b].x += x * wv.x; acc[b].y += x * wv.y;
            acc[b].z += x * wv.z; acc[b].w += x * wv.w;
        }
    }
    float ag = *ag_p;
#pragma unroll
    for (int b = 0; b < Bb; b++) {
        float* dst = g_addition + b * Dm + 4 * tid;
        atomicAdd(dst + 0, acc[b].x * ag); atomicAdd(dst + 1, acc[b].y * ag);
        atomicAdd(dst + 2, acc[b].z * ag); atomicAdd(dst + 3, acc[b].w * ag);
    }
}

// ---------------- output = bridge + addition (broadcast over T) ---------------
__global__ void __launch_bounds__(256) k_output(const float* __restrict__ bridge,
                                                float* __restrict__ out) {
    size_t i4 = (size_t)blockIdx.x * 256 + threadIdx.x;
    if (i4 >= (size_t)OUT_MAIN / 4) return;
    float4 br = reinterpret_cast<const float4*>(bridge)[i4];
    int b = (int)(i4 >> 19); // i4 / (T*Dm/4)
    int d4 = (int)(i4 & 255);
    if (g_count > 0.0f) {
        float4 ad = reinterpret_cast<const float4*>(g_addition)[b * 256 + d4];
        br.x += ad.x; br.y += ad.y; br.z += ad.z; br.w += ad.w;
    }
    reinterpret_cast<float4*>(out)[i4] = br;
}

// ---------------- launch ------------------------------------------------------
extern "C" void kernel_launch(void* const* d_in, const int* in_sizes, int n_in,
                              void* d_out, int out_size) {
    const float* bridge = (const float*)d_in[0];
    const float* eo     = (const float*)d_in[1];
    const float* ew     = (const float*)d_in[2];
    const float* q      = (const float*)d_in[3];
    const float* Wk     = (const float*)d_in[4];
    // d_in[5] = cond_bk: constant shift, softmax-invariant -> unused
    const float* Wv     = (const float*)d_in[6];
    const float* bv     = (const float*)d_in[7];
    const float* Wa     = (const float*)d_in[8];
    const float* ba     = (const float*)d_in[9];
    const float* Wb     = (const float*)d_in[10];
    const float* bb     = (const float*)d_in[11];
    const float* gW1    = (const float*)d_in[12];
    const float* gb1    = (const float*)d_in[13];
    const float* gW2    = (const float*)d_in[14];
    const float* gb2    = (const float*)d_in[15];
    const float* sW1    = (const float*)d_in[16];
    const float* sb1    = (const float*)d_in[17];
    const float* sW2    = (const float*)d_in[18];
    const float* sb2    = (const float*)d_in[19];
    const float* pg     = (const float*)d_in[20];
    const float* gamma  = (const float*)d_in[21];
    const float* beta   = (const float*)d_in[22];
    const float* outW   = (const float*)d_in[23];
    const float* outb   = (const float*)d_in[24];
    const float* agate  = (const float*)d_in[25];
    float* out = (float*)d_out;

    int init_n = Ee * Bb * Dm + Pp * Bb * 1024 + Pp * Bb * DAa + Pp * Bb * Dm + Bb * Dm;
    k_init<<<(init_n + 255) / 256, 256>>>(bv, ba, bb, gb1, sb1);
    k_u<<<(Ee * Dm + 7) / 8, 256>>>(Wk, q);
    k_condense<<<Ee * Bb * NCHUNK, 256>>>(eo, ew);
    k_combine<<<Ee * Bb, 256>>>();
    k_form<<<Ee * 8, 256>>>(Wv);
    k_pair_ab<<<Pp * 8, 128>>>(Wa, Wb);
    k_gate1<<<Pp * 4, 128>>>(gW1);
    k_syn1<<<Pp * 8, 256>>>(sW1);
    k_act_hs<<<(Pp * Bb * Dm + 255) / 256, 256>>>();
    k_strength<<<Pp, 128>>>(gW2, gb2, pg);
    k_count<<<1, 64>>>(out, out_size);
    k_biastotal<<<(Bb * Dm + 255) / 256, 256>>>(sb2);
    k_syn2<<<Pp * 8, 256>>>(sW2);
    k_ln<<<1, 256>>>(gamma, beta, outb, agate);
    k_proj<<<8, 256>>>(outW, agate);
    k_output<<<(OUT_MAIN / 4 + 255) / 256, 256>>>(bridge, out);
}

// round 2
// speedup vs baseline: 1.7516x; 1.7516x over previous
#include <cuda_runtime.h>
#include <math.h>

#define Bb 4
#define Tt 2048
#define Dm 1024
#define Ee 6
#define Pp 36
#define DAa 512
#define NCHUNK 32
#define RPC (Tt / NCHUNK) // 64 rows per chunk
#define THRESH 0.3f
#define LN_EPS 1e-5f
#define OUT_MAIN (Bb * Tt * Dm) // 8388608

// ---------------- scratch (static device globals; no allocation) -------------
__device__ float g_u[Ee * Dm];
__device__ float g_pm[Ee * Bb * NCHUNK];
__device__ float g_ps[Ee * Bb * NCHUNK];
__device__ float g_pacc[Ee * Bb * NCHUNK * Dm]; // 3 MB
__device__ float g_y[Ee * Bb * Dm];
__device__ float g_form[Ee * Bb * Dm];
__device__ float g_c[Pp * Bb * 2 * DAa];
__device__ float g_hpre[Pp * Bb * DAa];
__device__ float g_hs[Pp * Bb * Dm];
__device__ float g_avg[Pp];
__device__ float g_scalepb[Pp * Bb]; // mask * pair_gate * strength
__device__ float g_count;
__device__ float g_total[Bb * Dm];
__device__ float g_normed[Bb * Dm];
__device__ float g_addition[Bb * Dm];

__device__ __forceinline__ float gelu_exact(float x) {
    return 0.5f * x * (1.0f + erff(x * 0.70710678118654752f));
}

// ---------------- init accumulators with biases ------------------------------
__global__ void k_init(const float* __restrict__ bv, const float* __restrict__ ba,
                       const float* __restrict__ bb, const float* __restrict__ gb1,
                       const float* __restrict__ sb1) {
    int i = blockIdx.x * blockDim.x + threadIdx.x;
    if (i < Ee * Bb * Dm) {
        int e = i / (Bb * Dm);
        int f = i % Dm;
        g_form[i] = bv[e * Dm + f];
        return;
    }
    i -= Ee * Bb * Dm;
    if (i < Pp * Bb * 1024) {
        int p = i / (Bb * 1024);
        int j = i % 1024;
        g_c[i] = (j < DAa) ? ba[p * DAa + j] : bb[p * DAa + (j - DAa)];
        return;
    }
    i -= Pp * Bb * 1024;
    if (i < Pp * Bb * DAa) {
        int p = i / (Bb * DAa);
        int a = i % DAa;
        g_hpre[i] = gb1[p * DAa + a];
        return;
    }
    i -= Pp * Bb * DAa;
    if (i < Pp * Bb * Dm) {
        int p = i / (Bb * Dm);
        int d = i % Dm;
        g_hs[i] = sb1[p * Dm + d];
        return;
    }
    i -= Pp * Bb * Dm;
    if (i < Bb * Dm) g_total[i] = 0.0f;
}

// ---------------- u[e,d] = scale * sum_f Wk[e,d,f] * q[e,f] ------------------
__global__ void k_u(const float* __restrict__ Wk, const float* __restrict__ q) {
    int warp = (blockIdx.x * blockDim.x + threadIdx.x) >> 5;
    int lane = threadIdx.x & 31;
    if (warp >= Ee * Dm) return;
    int e = warp / Dm, d = warp % Dm;
    const float4* w4 = reinterpret_cast<const float4*>(Wk + ((size_t)e * Dm + d) * Dm);
    const float4* q4 = reinterpret_cast<const float4*>(q + e * Dm);
    float s = 0.0f;
#pragma unroll
    for (int f = lane; f < Dm / 4; f += 32) {
        float4 a = w4[f], b = q4[f];
        s += a.x * b.x + a.y * b.y + a.z * b.z + a.w * b.w;
    }
#pragma unroll
    for (int o = 16; o; o >>= 1) s += __shfl_down_sync(0xffffffffu, s, o);
    if (!lane) g_u[warp] = s * 0.03125f; // D^-0.5 = 1/32
}

// ---------------- fused condenser: one pass, online softmax, 8-row batches ----
__global__ void __launch_bounds__(256) k_condense(const float* __restrict__ eo,
                                                  const float* __restrict__ ew) {
    int bid = blockIdx.x;
    int chunk = bid % NCHUNK;
    int eb = bid / NCHUNK;
    int e = eb / Bb, b = eb % Bb;
    int tid = threadIdx.x;
    int lane = tid & 31, warp = tid >> 5;
    __shared__ float s_part[8][9]; // [row][warp] padded
    __shared__ float s_logit[8];
    __shared__ float s_w[RPC];
    if (tid < RPC) {
        int t = chunk * RPC + tid;
        s_w[tid] = ew[((size_t)b * Tt + t) * Ee + e];
    }
    float4 uv = reinterpret_cast<const float4*>(g_u + e * Dm)[tid];
    const float4* xbase = reinterpret_cast<const float4*>(
        eo + (((size_t)e * Bb + b) * Tt + (size_t)chunk * RPC) * Dm);
    __syncthreads();

    float m = -1e30f, ssum = 0.0f;
    float4 acc = {0.f, 0.f, 0.f, 0.f};
    for (int g = 0; g < RPC / 8; ++g) {
        float4 xv[8];
#pragma unroll
        for (int r = 0; r < 8; r++)
            xv[r] = xbase[(size_t)(g * 8 + r) * 256 + tid];
        float pd[8];
#pragma unroll
        for (int r = 0; r < 8; r++)
            pd[r] = xv[r].x * uv.x + xv[r].y * uv.y + xv[r].z * uv.z + xv[r].w * uv.w;
#pragma unroll
        for (int r = 0; r < 8; r++) {
#pragma unroll
            for (int o = 16; o; o >>= 1) pd[r] += __shfl_down_sync(0xffffffffu, pd[r], o);
        }
        if (lane == 0) {
#pragma unroll
            for (int r = 0; r < 8; r++) s_part[r][warp] = pd[r];
        }
        __syncthreads();
        if (tid < 8) {
            float t = 0.0f;
#pragma unroll
            for (int k = 0; k < 8; k++) t += s_part[tid][k];
            s_logit[tid] = t * s_w[g * 8 + tid];
        }
        __syncthreads();
#pragma unroll
        for (int r = 0; r < 8; r++) {
            float w = s_w[g * 8 + r];
            float l = s_logit[r];
            if (l > m) {
                float f = __expf(m - l);
                acc.x *= f; acc.y *= f; acc.z *= f; acc.w *= f;
                ssum *= f;
                m = l;
            }
            float pe = __expf(l - m);
            ssum += pe;
            float cf = pe * w;
            acc.x += cf * xv[r].x; acc.y += cf * xv[r].y;
            acc.z += cf * xv[r].z; acc.w += cf * xv[r].w;
        }
        __syncthreads();
    }
    if (tid == 0) {
        g_pm[bid] = m;
        g_ps[bid] = ssum;
    }
    reinterpret_cast<float4*>(g_pacc + (size_t)bid * Dm)[tid] = acc;
}

// ---------------- combine split-softmax partials -> y (24 x 1024 thr) --------
__global__ void __launch_bounds__(1024) k_combine() {
    int eb = blockIdx.x;
    int tid = threadIdx.x;
    int col = tid & 255, cg = tid >> 8; // 4 chunk-groups of 8
    __shared__ float4 s_acc[3][256];
    float M = -1e30f;
#pragma unroll
    for (int c = 0; c < NCHUNK; c++) M = fmaxf(M, g_pm[eb * NCHUNK + c]);
    float S = 0.0f;
#pragma unroll
    for (int c = 0; c < NCHUNK; c++) S += g_ps[eb * NCHUNK + c] * __expf(g_pm[eb * NCHUNK + c] - M);
    float4 y = {0.f, 0.f, 0.f, 0.f};
#pragma unroll
    for (int k = 0; k < 8; k++) {
        int c = cg * 8 + k;
        int pidx = eb * NCHUNK + c;
        float f = __expf(g_pm[pidx] - M);
        float4 a = reinterpret_cast<const float4*>(g_pacc + (size_t)pidx * Dm)[col];
        y.x += a.x * f; y.y += a.y * f; y.z += a.z * f; y.w += a.w * f;
    }
    if (cg > 0) s_acc[cg - 1][col] = y;
    __syncthreads();
    if (cg == 0) {
#pragma unroll
        for (int j = 0; j < 3; j++) {
            float4 a = s_acc[j][col];
            y.x += a.x; y.y += a.y; y.z += a.z; y.w += a.w;
        }
        float inv = 1.0f / S;
        y.x *= inv; y.y *= inv; y.z *= inv; y.w *= inv;
        reinterpret_cast<float4*>(g_y + (size_t)eb * Dm)[col] = y;
    }
}

// ---------------- formulas = y @ Wv (+bv already in g_form) ------------------
__global__ void __launch_bounds__(256) k_form(const float* __restrict__ Wv) {
    int e = blockIdx.x >> 5, ds = blockIdx.x & 31; // 32 rows each
    int tid = threadIdx.x;
    __shared__ float s_in[Bb * Dm];
#pragma unroll
    for (int k = tid; k < Bb * Dm / 4; k += 256)
        reinterpret_cast<float4*>(s_in)[k] =
            reinterpret_cast<const float4*>(g_y + (size_t)e * Bb * Dm)[k];
    __syncthreads();
    const float4* Wp = reinterpret_cast<const float4*>(Wv + (size_t)e * Dm * Dm);
    float4 acc[Bb] = {};
    int d0 = ds * 32;
#pragma unroll
    for (int dd = 0; dd < 32; dd += 8) {
        float4 w[8];
#pragma unroll
        for (int j = 0; j < 8; j++) w[j] = Wp[(size_t)(d0 + dd + j) * 256 + tid];
#pragma unroll
        for (int j = 0; j < 8; j++) {
#pragma unroll
            for (int b = 0; b < Bb; b++) {
                float x = s_in[b * Dm + d0 + dd + j];
                acc[b].x += x * w[j].x; acc[b].y += x * w[j].y;
                acc[b].z += x * w[j].z; acc[b].w += x * w[j].w;
            }
        }
    }
#pragma unroll
    for (int b = 0; b < Bb; b++) {
        float* dst = g_form + ((size_t)e * Bb + b) * Dm + 4 * tid;
        atomicAdd(dst + 0, acc[b].x); atomicAdd(dst + 1, acc[b].y);
        atomicAdd(dst + 2, acc[b].z); atomicAdd(dst + 3, acc[b].w);
    }
}

// ---------------- pair a/b projections: c[p] = [fa@Wa | fb@Wb] ---------------
// grid = Pp*2*4 = 288, block 256 (2 row-groups x 128 cols)
__global__ void __launch_bounds__(256) k_pair_ab(const float* __restrict__ Wa,
                                                 const float* __restrict__ Wb) {
    int bid = blockIdx.x;
    int ds = bid & 3;
    int half = (bid >> 2) & 1;
    int p = bid >> 3;
    int src = half ? (p % Ee) : (p / Ee); // PJ : PI
    const float4* Wp = reinterpret_cast<const float4*>(
        (half ? Wb : Wa) + (size_t)p * Dm * DAa);
    int tid = threadIdx.x;
    int col = tid & 127, rg = tid >> 7;
    __shared__ float s_in[Bb * Dm];
#pragma unroll
    for (int k = tid; k < Bb * Dm / 4; k += 256)
        reinterpret_cast<float4*>(s_in)[k] =
            reinterpret_cast<const float4*>(g_form + (size_t)src * Bb * Dm)[k];
    __syncthreads();
    float4 acc[Bb] = {};
    int d0 = ds * 256 + rg * 128;
#pragma unroll 4
    for (int dd = 0; dd < 128; dd += 8) {
        float4 w[8];
#pragma unroll
        for (int j = 0; j < 8; j++) w[j] = Wp[(size_t)(d0 + dd + j) * 128 + col];
#pragma unroll
        for (int j = 0; j < 8; j++) {
#pragma unroll
            for (int b = 0; b < Bb; b++) {
                float x = s_in[b * Dm + d0 + dd + j];
                acc[b].x += x * w[j].x; acc[b].y += x * w[j].y;
                acc[b].z += x * w[j].z; acc[b].w += x * w[j].w;
            }
        }
    }
#pragma unroll
    for (int b = 0; b < Bb; b++) {
        float* dst = g_c + ((size_t)p * Bb + b) * 1024 + half * DAa + 4 * col;
        atomicAdd(dst + 0, acc[b].x); atomicAdd(dst + 1, acc[b].y);
        atomicAdd(dst + 2, acc[b].z); atomicAdd(dst + 3, acc[b].w);
    }
}

// ---------------- gate pre-activation: hpre = c @ gate_W1 --------------------
// grid = Pp*8 = 288, block 256 (2 row-groups of 64 x 128 cols)
__global__ void __launch_bounds__(256) k_gate1(const float* __restrict__ gW1) {
    int bid = blockIdx.x;
    int ds = bid & 7;
    int p = bid >> 3;
    int tid = threadIdx.x;
    int col = tid & 127, rg = tid >> 7;
    __shared__ float s_in[Bb * 1024];
#pragma unroll
    for (int k = tid; k < Bb * 1024 / 4; k += 256)
        reinterpret_cast<float4*>(s_in)[k] =
            reinterpret_cast<const float4*>(g_c + (size_t)p * Bb * 1024)[k];
    __syncthreads();
    const float4* Wp = reinterpret_cast<const float4*>(gW1 + (size_t)p * 1024 * DAa);
    float4 acc[Bb] = {};
    int d0 = ds * 128 + rg * 64;
#pragma unroll 4
    for (int dd = 0; dd < 64; dd += 8) {
        float4 w[8];
#pragma unroll
        for (int j = 0; j < 8; j++) w[j] = Wp[(size_t)(d0 + dd + j) * 128 + col];
#pragma unroll
        for (int j = 0; j < 8; j++) {
#pragma unroll
            for (int b = 0; b < Bb; b++) {
                float x = s_in[b * 1024 + d0 + dd + j];
                acc[b].x += x * w[j].x; acc[b].y += x * w[j].y;
                acc[b].z += x * w[j].z; acc[b].w += x * w[j].w;
            }
        }
    }
#pragma unroll
    for (int b = 0; b < Bb; b++) {
        float* dst = g_hpre + ((size_t)p * Bb + b) * DAa + 4 * col;
        atomicAdd(dst + 0, acc[b].x); atomicAdd(dst + 1, acc[b].y);
        atomicAdd(dst + 2, acc[b].z); atomicAdd(dst + 3, acc[b].w);
    }
}

// ---------------- syn hidden pre-activation: g_hs += c @ syn_W1 --------------
// grid = Pp*8 = 288, block 256 (256 cols, 128 rows each)
__global__ void __launch_bounds__(256) k_syn1(const float* __restrict__ sW1) {
    int bid = blockIdx.x;
    int ds = bid & 7;
    int p = bid >> 3;
    int tid = threadIdx.x;
    __shared__ float s_in[Bb * 1024];
#pragma unroll
    for (int k = tid; k < Bb * 1024 / 4; k += 256)
        reinterpret_cast<float4*>(s_in)[k] =
            reinterpret_cast<const float4*>(g_c + (size_t)p * Bb * 1024)[k];
    __syncthreads();
    const float4* Wp = reinterpret_cast<const float4*>(sW1 + (size_t)p * 1024 * Dm);
    float4 acc[Bb] = {};
    int d0 = ds * 128;
#pragma unroll 2
    for (int dd = 0; dd < 128; dd += 8) {
        float4 w[8];
#pragma unroll
        for (int j = 0; j < 8; j++) w[j] = Wp[(size_t)(d0 + dd + j) * 256 + tid];
#pragma unroll
        for (int j = 0; j < 8; j++) {
#pragma unroll
            for (int b = 0; b < Bb; b++) {
                float x = s_in[b * 1024 + d0 + dd + j];
                acc[b].x += x * w[j].x; acc[b].y += x * w[j].y;
                acc[b].z += x * w[j].z; acc[b].w += x * w[j].w;
            }
        }
    }
#pragma unroll
    for (int b = 0; b < Bb; b++) {
        float* dst = g_hs + ((size_t)p * Bb + b) * Dm + 4 * tid;
        atomicAdd(dst + 0, acc[b].x); atomicAdd(dst + 1, acc[b].y);
        atomicAdd(dst + 2, acc[b].z); atomicAdd(dst + 3, acc[b].w);
    }
}

// ---------------- strength = sigmoid(gelu(hpre) @ gate_W2 + b2) --------------
__global__ void __launch_bounds__(128) k_strength(const float* __restrict__ gW2,
                                                  const float* __restrict__ gb2,
                                                  const float* __restrict__ pg) {
    int p = blockIdx.x, tid = threadIdx.x;
    float part[Bb] = {0.f, 0.f, 0.f, 0.f};
    for (int a = tid; a < DAa; a += 128) {
        float w2 = gW2[p * DAa + a];
#pragma unroll
        for (int b = 0; b < Bb; b++) {
            float h = g_hpre[((size_t)p * Bb + b) * DAa + a];
            part[b] += gelu_exact(h) * w2;
        }
    }
    __shared__ float s_red[Bb][4];
#pragma unroll
    for (int b = 0; b < Bb; b++) {
        float v = part[b];
#pragma unroll
        for (int o = 16; o; o >>= 1) v += __shfl_down_sync(0xffffffffu, v, o);
        if ((tid & 31) == 0) s_red[b][tid >> 5] = v;
    }
    __syncthreads();
    if (tid == 0) {
        float avg = 0.0f;
        float st[Bb];
#pragma unroll
        for (int b = 0; b < Bb; b++) {
            float d = s_red[b][0] + s_red[b][1] + s_red[b][2] + s_red[b][3] + gb2[p];
            st[b] = 1.0f / (1.0f + expf(-d));
            avg += st[b];
        }
        avg *= 0.25f;
        g_avg[p] = avg;
        float mk = (avg > THRESH) ? pg[p] : 0.0f;
#pragma unroll
        for (int b = 0; b < Bb; b++)
            g_scalepb[p * Bb + b] = mk * st[b];
    }
}

// ---------------- count actives; write aux outputs ----------------------------
__global__ void k_count(float* __restrict__ out, int out_size) {
    if (threadIdx.x == 0) {
        float c = 0.0f;
        for (int p = 0; p < Pp; p++) c += (g_avg[p] > THRESH) ? 1.0f : 0.0f;
        g_count = c;
        if (out_size >= OUT_MAIN + Pp + 1) out[OUT_MAIN + Pp] = c;
    }
    if (threadIdx.x < Pp && out_size >= OUT_MAIN + Pp + 1)
        out[OUT_MAIN + threadIdx.x] = g_avg[threadIdx.x];
}

// ---------------- total bias term: sum_p scale_pb * syn_b2 -------------------
__global__ void k_biastotal(const float* __restrict__ sb2) {
    int i = blockIdx.x * blockDim.x + threadIdx.x;
    if (i >= Bb * Dm) return;
    int b = i >> 10;
    int j = i & 1023;
    float s = 0.0f;
#pragma unroll
    for (int p = 0; p < Pp; p++) s += g_scalepb[p * Bb + b] * sb2[p * Dm + j];
    g_total[i] = s;
}

// ---------------- total += scale_pb * (gelu(hs) @ syn_W2) --------------------
// grid = Pp*8 = 288, block 256; gelu folded into staging
__global__ void __launch_bounds__(256) k_syn2(const float* __restrict__ sW2) {
    int bid = blockIdx.x;
    int ds = bid & 7;
    int p = bid >> 3;
    int tid = threadIdx.x;
    __shared__ float s_in[Bb * Dm];
#pragma unroll
    for (int k = tid; k < Bb * Dm / 4; k += 256) {
        float4 v = reinterpret_cast<const float4*>(g_hs + (size_t)p * Bb * Dm)[k];
        v.x = gelu_exact(v.x); v.y = gelu_exact(v.y);
        v.z = gelu_exact(v.z); v.w = gelu_exact(v.w);
        reinterpret_cast<float4*>(s_in)[k] = v;
    }
    __syncthreads();
    const float4* Wp = reinterpret_cast<const float4*>(sW2 + (size_t)p * Dm * Dm);
    float4 acc[Bb] = {};
    int d0 = ds * 128;
#pragma unroll 2
    for (int dd = 0; dd < 128; dd += 8) {
        float4 w[8];
#pragma unroll
        for (int j = 0; j < 8; j++) w[j] = Wp[(size_t)(d0 + dd + j) * 256 + tid];
#pragma unroll
        for (int j = 0; j < 8; j++) {
#pragma unroll
            for (int b = 0; b < Bb; b++) {
                float x = s_in[b * Dm + d0 + dd + j];
                acc[b].x += x * w[j].x; acc[b].y += x * w[j].y;
                acc[b].z += x * w[j].z; acc[b].w += x * w[j].w;
            }
        }
    }
#pragma unroll
    for (int b = 0; b < Bb; b++) {
        float sc = g_scalepb[p * Bb + b];
        float* dst = g_total + b * Dm + 4 * tid;
        atomicAdd(dst + 0, acc[b].x * sc); atomicAdd(dst + 1, acc[b].y * sc);
        atomicAdd(dst + 2, acc[b].z * sc); atomicAdd(dst + 3, acc[b].w * sc);
    }
}

// ---------------- LayerNorm(total / max(count,1)) -----------------------------
__global__ void __launch_bounds__(256) k_ln(const float* __restrict__ gamma,
                                            const float* __restrict__ beta,
                                            const float* __restrict__ out_b,
                                            const float* __restrict__ ag_p) {
    int tid = threadIdx.x;
    __shared__ float s_red[8];
    __shared__ float s_stat;
    float inv_cnt = 1.0f / fmaxf(g_count, 1.0f);
    float ag = *ag_p;
    float4 ga = reinterpret_cast<const float4*>(gamma)[tid];
    float4 be = reinterpret_cast<const float4*>(beta)[tid];
    for (int b = 0; b < Bb; b++) {
        float4 v = reinterpret_cast<const float4*>(g_total + b * Dm)[tid];
        v.x *= inv_cnt; v.y *= inv_cnt; v.z *= inv_cnt; v.w *= inv_cnt;
        float lsum = v.x + v.y + v.z + v.w;
#pragma unroll
        for (int o = 16; o; o >>= 1) lsum += __shfl_down_sync(0xffffffffu, lsum, o);
        if ((tid & 31) == 0) s_red[tid >> 5] = lsum;
        __syncthreads();
        if (tid == 0) {
            float t = 0;
#pragma unroll
            for (int k = 0; k < 8; k++) t += s_red[k];
            s_stat = t * (1.0f / Dm);
        }
        __syncthreads();
        float mu = s_stat;
        __syncthreads();
        float dx = v.x - mu, dy = v.y - mu, dz = v.z - mu, dw = v.w - mu;
        float lsq = dx * dx + dy * dy + dz * dz + dw * dw;
#pragma unroll
        for (int o = 16; o; o >>= 1) lsq += __shfl_down_sync(0xffffffffu, lsq, o);
        if ((tid & 31) == 0) s_red[tid >> 5] = lsq;
        __syncthreads();
        if (tid == 0) {
            float t = 0;
#pragma unroll
            for (int k = 0; k < 8; k++) t += s_red[k];
            s_stat = t * (1.0f / Dm);
        }
        __syncthreads();
        float rstd = rsqrtf(s_stat + LN_EPS);
        __syncthreads();
        float4 nv;
        nv.x = dx * rstd * ga.x + be.x;
        nv.y = dy * rstd * ga.y + be.y;
        nv.z = dz * rstd * ga.z + be.z;
        nv.w = dw * rstd * ga.w + be.w;
        reinterpret_cast<float4*>(g_normed + b * Dm)[tid] = nv;
    }
    float4 ob = reinterpret_cast<const float4*>(out_b)[tid];
    ob.x *= ag; ob.y *= ag; ob.z *= ag; ob.w *= ag;
#pragma unroll
    for (int b = 0; b < Bb; b++)
        reinterpret_cast<float4*>(g_addition + b * Dm)[tid] = ob;
}

// ---------------- addition += (normed @ out_W) * gate -------------------------
// grid = 32, block 256 (32 rows each)
__global__ void __launch_bounds__(256) k_proj(const float* __restrict__ out_W,
                                              const float* __restrict__ ag_p) {
    int ds = blockIdx.x;
    int tid = threadIdx.x;
    __shared__ float s_in[Bb * Dm];
#pragma unroll
    for (int k = tid; k < Bb * Dm / 4; k += 256)
        reinterpret_cast<float4*>(s_in)[k] = reinterpret_cast<const float4*>(g_normed)[k];
    __syncthreads();
    const float4* Wp = reinterpret_cast<const float4*>(out_W);
    float4 acc[Bb] = {};
    int d0 = ds * 32;
#pragma unroll
    for (int dd = 0; dd < 32; dd += 8) {
        float4 w[8];
#pragma unroll
        for (int j = 0; j < 8; j++) w[j] = Wp[(size_t)(d0 + dd + j) * 256 + tid];
#pragma unroll
        for (int j = 0; j < 8; j++) {
#pragma unroll
            for (int b = 0; b < Bb; b++) {
                float x = s_in[b * Dm + d0 + dd + j];
                acc[b].x += x * w[j].x; acc[b].y += x * w[j].y;
                acc[b].z += x * w[j].z; acc[b].w += x * w[j].w;
            }
        }
    }
    float ag = *ag_p;
#pragma unroll
    for (int b = 0; b < Bb; b++) {
        float* dst = g_addition + b * Dm + 4 * tid;
        atomicAdd(dst + 0, acc[b].x * ag); atomicAdd(dst + 1, acc[b].y * ag);
        atomicAdd(dst + 2, acc[b].z * ag); atomicAdd(dst + 3, acc[b].w * ag);
    }
}

// ---------------- output = bridge + addition (broadcast over T) ---------------
__global__ void __launch_bounds__(256) k_output(const float* __restrict__ bridge,
                                                float* __restrict__ out) {
    size_t i4 = (size_t)blockIdx.x * 256 + threadIdx.x;
    if (i4 >= (size_t)OUT_MAIN / 4) return;
    float4 br = reinterpret_cast<const float4*>(bridge)[i4];
    int b = (int)(i4 >> 19);
    int d4 = (int)(i4 & 255);
    if (g_count > 0.0f) {
        float4 ad = reinterpret_cast<const float4*>(g_addition)[b * 256 + d4];
        br.x += ad.x; br.y += ad.y; br.z += ad.z; br.w += ad.w;
    }
    reinterpret_cast<float4*>(out)[i4] = br;
}

// ---------------- launch ------------------------------------------------------
extern "C" void kernel_launch(void* const* d_in, const int* in_sizes, int n_in,
                              void* d_out, int out_size) {
    const float* bridge = (const float*)d_in[0];
    const float* eo     = (const float*)d_in[1];
    const float* ew     = (const float*)d_in[2];
    const float* q      = (const float*)d_in[3];
    const float* Wk     = (const float*)d_in[4];
    const float* Wv     = (const float*)d_in[6];
    const float* bv     = (const float*)d_in[7];
    const float* Wa     = (const float*)d_in[8];
    const float* ba     = (const float*)d_in[9];
    const float* Wb     = (const float*)d_in[10];
    const float* bb     = (const float*)d_in[11];
    const float* gW1    = (const float*)d_in[12];
    const float* gb1    = (const float*)d_in[13];
    const float* gW2    = (const float*)d_in[14];
    const float* gb2    = (const float*)d_in[15];
    const float* sW1    = (const float*)d_in[16];
    const float* sb1    = (const float*)d_in[17];
    const float* sW2    = (const float*)d_in[18];
    const float* sb2    = (const float*)d_in[19];
    const float* pg     = (const float*)d_in[20];
    const float* gamma  = (const float*)d_in[21];
    const float* beta   = (const float*)d_in[22];
    const float* outW   = (const float*)d_in[23];
    const float* outb   = (const float*)d_in[24];
    const float* agate  = (const float*)d_in[25];
    float* out = (float*)d_out;

    int init_n = Ee * Bb * Dm + Pp * Bb * 1024 + Pp * Bb * DAa + Pp * Bb * Dm + Bb * Dm;
    k_init<<<(init_n + 255) / 256, 256>>>(bv, ba, bb, gb1, sb1);
    k_u<<<(Ee * Dm + 7) / 8, 256>>>(Wk, q);
    k_condense<<<Ee * Bb * NCHUNK, 256>>>(eo, ew);
    k_combine<<<Ee * Bb, 1024>>>();
    k_form<<<Ee * 32, 256>>>(Wv);
    k_pair_ab<<<Pp * 8, 256>>>(Wa, Wb);
    k_syn1<<<Pp * 8, 256>>>(sW1);
    k_gate1<<<Pp * 8, 256>>>(gW1);
    k_strength<<<Pp, 128>>>(gW2, gb2, pg);
    k_count<<<1, 64>>>(out, out_size);
    k_biastotal<<<(Bb * Dm + 255) / 256, 256>>>(sb2);
    k_syn2<<<Pp * 8, 256>>>(sW2);
    k_ln<<<1, 256>>>(gamma, beta, outb, agate);
    k_proj<<<32, 256>>>(outW, agate);
    k_output<<<(OUT_MAIN / 4 + 255) / 256, 256>>>(bridge, out);
}

// round 3
// speedup vs baseline: 1.7541x; 1.0014x over previous
#include <cuda_runtime.h>
#include <math.h>

#define Bb 4
#define Tt 2048
#define Dm 1024
#define Ee 6
#define Pp 36
#define DAa 512
#define NCHUNK 32
#define RPC (Tt / NCHUNK) // 64 rows per chunk
#define THRESH 0.3f
#define LN_EPS 1e-5f
#define OUT_MAIN (Bb * Tt * Dm) // 8388608

// ---------------- scratch ------------------------------------------------------
__device__ float g_u[Ee * Dm];
__device__ float g_ps[Ee * Bb * NCHUNK];
__device__ float g_pacc[Ee * Bb * NCHUNK * Dm]; // 3 MB
__device__ float g_y[Ee * Bb * Dm];
__device__ float g_form[Ee * Bb * Dm];
__device__ float g_c[Pp * Bb * 2 * DAa];
__device__ float g_hpre[Pp * Bb * DAa];
__device__ float g_hs[Pp * Bb * Dm];
__device__ float g_scalepb[Pp * Bb];
__device__ float g_count;
__device__ float g_total[Bb * Dm];
__device__ float g_normed[Bb * Dm];
__device__ float g_addition[Bb * Dm];

__device__ __forceinline__ float gelu_exact(float x) {
    return 0.5f * x * (1.0f + erff(x * 0.70710678118654752f));
}

// ---------------- init accumulators with biases -------------------------------
__global__ void k_init(const float* __restrict__ bv, const float* __restrict__ ba,
                       const float* __restrict__ bb, const float* __restrict__ gb1,
                       const float* __restrict__ sb1) {
    int i = blockIdx.x * blockDim.x + threadIdx.x;
    if (i == 0) g_count = 0.0f;
    if (i < Ee * Bb * Dm) {
        int e = i / (Bb * Dm);
        int f = i % Dm;
        g_form[i] = bv[e * Dm + f];
        return;
    }
    i -= Ee * Bb * Dm;
    if (i < Pp * Bb * 1024) {
        int p = i / (Bb * 1024);
        int j = i % 1024;
        g_c[i] = (j < DAa) ? ba[p * DAa + j] : bb[p * DAa + (j - DAa)];
        return;
    }
    i -= Pp * Bb * 1024;
    if (i < Pp * Bb * DAa) {
        int p = i / (Bb * DAa);
        int a = i % DAa;
        g_hpre[i] = gb1[p * DAa + a];
        return;
    }
    i -= Pp * Bb * DAa;
    if (i < Pp * Bb * Dm) {
        int p = i / (Bb * Dm);
        int d = i % Dm;
        g_hs[i] = sb1[p * Dm + d];
        return;
    }
    i -= Pp * Bb * Dm;
    if (i < Bb * Dm) g_total[i] = 0.0f;
}

// ---------------- u[e,d] = scale * sum_f Wk[e,d,f] * q[e,f] --------------------
__global__ void k_u(const float* __restrict__ Wk, const float* __restrict__ q) {
    int warp = (blockIdx.x * blockDim.x + threadIdx.x) >> 5;
    int lane = threadIdx.x & 31;
    if (warp >= Ee * Dm) return;
    int e = warp / Dm, d = warp % Dm;
    const float4* w4 = reinterpret_cast<const float4*>(Wk + ((size_t)e * Dm + d) * Dm);
    const float4* q4 = reinterpret_cast<const float4*>(q + e * Dm);
    float s = 0.0f;
#pragma unroll
    for (int f = lane; f < Dm / 4; f += 32) {
        float4 a = w4[f], b = q4[f];
        s += a.x * b.x + a.y * b.y + a.z * b.z + a.w * b.w;
    }
#pragma unroll
    for (int o = 16; o; o >>= 1) s += __shfl_down_sync(0xffffffffu, s, o);
    if (!lane) g_u[warp] = s * 0.03125f;
}

// ---------------- condenser: warp-per-row, no block barriers in loop -----------
__global__ void __launch_bounds__(256) k_condense(const float* __restrict__ eo,
                                                  const float* __restrict__ ew) {
    int bid = blockIdx.x;
    int chunk = bid % NCHUNK;
    int eb = bid / NCHUNK;
    int e = eb / Bb, b = eb % Bb;
    int tid = threadIdx.x;
    int lane = tid & 31, warp = tid >> 5;
    __shared__ float s_w[RPC];
    __shared__ float4 s_acc[8 * 256]; // 32 KB
    __shared__ float s_sum[8];
    if (tid < RPC) {
        int t = chunk * RPC + tid;
        s_w[tid] = ew[((size_t)b * Tt + t) * Ee + e];
    }
    float4 uv[8];
    const float4* u4 = reinterpret_cast<const float4*>(g_u) + e * 256;
#pragma unroll
    for (int k = 0; k < 8; k++) uv[k] = u4[lane + 32 * k];
    const float4* xbase = reinterpret_cast<const float4*>(eo) +
        (((size_t)e * Bb + b) * Tt + (size_t)chunk * RPC) * 256;
    __syncthreads();

    float ssum = 0.0f;
    float4 acc[8] = {};
#pragma unroll
    for (int r8 = 0; r8 < 8; ++r8) {
        int row = r8 * 8 + warp;
        const float4* rp = xbase + (size_t)row * 256;
        float4 xv[8];
#pragma unroll
        for (int k = 0; k < 8; k++) xv[k] = rp[lane + 32 * k];
        float d = 0.0f;
#pragma unroll
        for (int k = 0; k < 8; k++)
            d += xv[k].x * uv[k].x + xv[k].y * uv[k].y + xv[k].z * uv[k].z + xv[k].w * uv[k].w;
#pragma unroll
        for (int o = 16; o; o >>= 1) d += __shfl_xor_sync(0xffffffffu, d, o);
        float w = s_w[row];
        float eexp = __expf(d * w); // |d*w| << 1 by construction: exact softmax
        ssum += eexp;
        float cf = eexp * w;
#pragma unroll
        for (int k = 0; k < 8; k++) {
            acc[k].x += cf * xv[k].x; acc[k].y += cf * xv[k].y;
            acc[k].z += cf * xv[k].z; acc[k].w += cf * xv[k].w;
        }
    }
#pragma unroll
    for (int k = 0; k < 8; k++) s_acc[warp * 256 + lane + 32 * k] = acc[k];
    if (lane == 0) s_sum[warp] = ssum;
    __syncthreads();
    float4 tot = {0.f, 0.f, 0.f, 0.f};
#pragma unroll
    for (int w = 0; w < 8; w++) {
        float4 a = s_acc[w * 256 + tid];
        tot.x += a.x; tot.y += a.y; tot.z += a.z; tot.w += a.w;
    }
    reinterpret_cast<float4*>(g_pacc)[(size_t)bid * 256 + tid] = tot;
    if (tid == 0) {
        float t = 0;
#pragma unroll
        for (int w = 0; w < 8; w++) t += s_sum[w];
        g_ps[bid] = t;
    }
}

// ---------------- combine partials -> y (96 blocks) ----------------------------
__global__ void __launch_bounds__(256) k_combine() {
    int eb = blockIdx.x >> 2, q = blockIdx.x & 3;
    int tid = threadIdx.x;
    int col = (tid & 63) + q * 64, cg = tid >> 6; // 4 groups of 8 chunks
    __shared__ float4 s_acc[3][64];
    float S = 0.0f;
#pragma unroll
    for (int c = 0; c < NCHUNK; c++) S += g_ps[eb * NCHUNK + c];
    float4 y = {0.f, 0.f, 0.f, 0.f};
#pragma unroll
    for (int k = 0; k < 8; k++) {
        int pidx = eb * NCHUNK + cg * 8 + k;
        float4 a = reinterpret_cast<const float4*>(g_pacc)[(size_t)pidx * 256 + col];
        y.x += a.x; y.y += a.y; y.z += a.z; y.w += a.w;
    }
    if (cg > 0) s_acc[cg - 1][tid & 63] = y;
    __syncthreads();
    if (cg == 0) {
#pragma unroll
        for (int j = 0; j < 3; j++) {
            float4 a = s_acc[j][tid & 63];
            y.x += a.x; y.y += a.y; y.z += a.z; y.w += a.w;
        }
        float inv = 1.0f / S;
        y.x *= inv; y.y *= inv; y.z *= inv; y.w *= inv;
        reinterpret_cast<float4*>(g_y)[(size_t)eb * 256 + col] = y;
    }
}

// ---------------- formulas = y @ Wv -------------------------------------------
__global__ void __launch_bounds__(256) k_form(const float* __restrict__ Wv) {
    int e = blockIdx.x >> 5, ds = blockIdx.x & 31;
    int tid = threadIdx.x;
    __shared__ float s_in[Bb * Dm];
#pragma unroll
    for (int k = tid; k < Bb * Dm / 4; k += 256)
        reinterpret_cast<float4*>(s_in)[k] =
            reinterpret_cast<const float4*>(g_y + (size_t)e * Bb * Dm)[k];
    __syncthreads();
    const float4* Wp = reinterpret_cast<const float4*>(Wv + (size_t)e * Dm * Dm);
    float4 acc[Bb] = {};
    int d0 = ds * 32;
#pragma unroll
    for (int dd = 0; dd < 32; dd += 8) {
        float4 w[8];
#pragma unroll
        for (int j = 0; j < 8; j++) w[j] = Wp[(size_t)(d0 + dd + j) * 256 + tid];
#pragma unroll
        for (int j = 0; j < 8; j++) {
#pragma unroll
            for (int b = 0; b < Bb; b++) {
                float x = s_in[b * Dm + d0 + dd + j];
                acc[b].x += x * w[j].x; acc[b].y += x * w[j].y;
                acc[b].z += x * w[j].z; acc[b].w += x * w[j].w;
            }
        }
    }
#pragma unroll
    for (int b = 0; b < Bb; b++) {
        float* dst = g_form + ((size_t)e * Bb + b) * Dm + 4 * tid;
        atomicAdd(dst + 0, acc[b].x); atomicAdd(dst + 1, acc[b].y);
        atomicAdd(dst + 2, acc[b].z); atomicAdd(dst + 3, acc[b].w);
    }
}

// ---------------- pair projections: c[p] = [fa@Wa | fb@Wb] ---------------------
__global__ void __launch_bounds__(256) k_pair_ab(const float* __restrict__ Wa,
                                                 const float* __restrict__ Wb) {
    int bid = blockIdx.x;
    int ds = bid & 3;
    int half = (bid >> 2) & 1;
    int p = bid >> 3;
    int src = half ? (p % Ee) : (p / Ee);
    const float4* Wp = reinterpret_cast<const float4*>(
        (half ? Wb : Wa) + (size_t)p * Dm * DAa);
    int tid = threadIdx.x;
    int col = tid & 127, rg = tid >> 7;
    __shared__ float s_in[Bb * Dm];
#pragma unroll
    for (int k = tid; k < Bb * Dm / 4; k += 256)
        reinterpret_cast<float4*>(s_in)[k] =
            reinterpret_cast<const float4*>(g_form + (size_t)src * Bb * Dm)[k];
    __syncthreads();
    float4 acc[Bb] = {};
    int d0 = ds * 256 + rg * 128;
#pragma unroll 4
    for (int dd = 0; dd < 128; dd += 8) {
        float4 w[8];
#pragma unroll
        for (int j = 0; j < 8; j++) w[j] = Wp[(size_t)(d0 + dd + j) * 128 + col];
#pragma unroll
        for (int j = 0; j < 8; j++) {
#pragma unroll
            for (int b = 0; b < Bb; b++) {
                float x = s_in[b * Dm + d0 + dd + j];
                acc[b].x += x * w[j].x; acc[b].y += x * w[j].y;
                acc[b].z += x * w[j].z; acc[b].w += x * w[j].w;
            }
        }
    }
#pragma unroll
    for (int b = 0; b < Bb; b++) {
        float* dst = g_c + ((size_t)p * Bb + b) * 1024 + half * DAa + 4 * col;
        atomicAdd(dst + 0, acc[b].x); atomicAdd(dst + 1, acc[b].y);
        atomicAdd(dst + 2, acc[b].z); atomicAdd(dst + 3, acc[b].w);
    }
}

// ---------------- fused syn1 + gate1 (both read g_c) ---------------------------
// grid = Pp*16: t<8 -> syn1 ds=t; t>=8 -> gate1 ds=t-8
__global__ void __launch_bounds__(256) k_mlp1(const float* __restrict__ sW1,
                                              const float* __restrict__ gW1) {
    int bid = blockIdx.x;
    int t = bid & 15;
    int p = bid >> 4;
    int tid = threadIdx.x;
    __shared__ float s_in[Bb * 1024];
#pragma unroll
    for (int k = tid; k < Bb * 1024 / 4; k += 256)
        reinterpret_cast<float4*>(s_in)[k] =
            reinterpret_cast<const float4*>(g_c + (size_t)p * Bb * 1024)[k];
    __syncthreads();
    if (t < 8) { // syn1: W 1024x1024
        const float4* Wp = reinterpret_cast<const float4*>(sW1 + (size_t)p * 1024 * Dm);
        float4 acc[Bb] = {};
        int d0 = t * 128;
#pragma unroll 2
        for (int dd = 0; dd < 128; dd += 8) {
            float4 w[8];
#pragma unroll
            for (int j = 0; j < 8; j++) w[j] = Wp[(size_t)(d0 + dd + j) * 256 + tid];
#pragma unroll
            for (int j = 0; j < 8; j++) {
#pragma unroll
                for (int b = 0; b < Bb; b++) {
                    float x = s_in[b * 1024 + d0 + dd + j];
                    acc[b].x += x * w[j].x; acc[b].y += x * w[j].y;
                    acc[b].z += x * w[j].z; acc[b].w += x * w[j].w;
                }
            }
        }
#pragma unroll
        for (int b = 0; b < Bb; b++) {
            float* dst = g_hs + ((size_t)p * Bb + b) * Dm + 4 * tid;
            atomicAdd(dst + 0, acc[b].x); atomicAdd(dst + 1, acc[b].y);
            atomicAdd(dst + 2, acc[b].z); atomicAdd(dst + 3, acc[b].w);
        }
    } else { // gate1: W 1024x512
        int ds = t - 8;
        int col = tid & 127, rg = tid >> 7;
        const float4* Wp = reinterpret_cast<const float4*>(gW1 + (size_t)p * 1024 * DAa);
        float4 acc[Bb] = {};
        int d0 = ds * 128 + rg * 64;
#pragma unroll 4
        for (int dd = 0; dd < 64; dd += 8) {
            float4 w[8];
#pragma unroll
            for (int j = 0; j < 8; j++) w[j] = Wp[(size_t)(d0 + dd + j) * 128 + col];
#pragma unroll
            for (int j = 0; j < 8; j++) {
#pragma unroll
                for (int b = 0; b < Bb; b++) {
                    float x = s_in[b * 1024 + d0 + dd + j];
                    acc[b].x += x * w[j].x; acc[b].y += x * w[j].y;
                    acc[b].z += x * w[j].z; acc[b].w += x * w[j].w;
                }
            }
        }
#pragma unroll
        for (int b = 0; b < Bb; b++) {
            float* dst = g_hpre + ((size_t)p * Bb + b) * DAa + 4 * col;
            atomicAdd(dst + 0, acc[b].x); atomicAdd(dst + 1, acc[b].y);
            atomicAdd(dst + 2, acc[b].z); atomicAdd(dst + 3, acc[b].w);
        }
    }
}

// ---------------- strength + scalepb + bias-total + count + aux out -----------
__global__ void __launch_bounds__(128) k_strength(const float* __restrict__ gW2,
                                                  const float* __restrict__ gb2,
                                                  const float* __restrict__ pg,
                                                  const float* __restrict__ sb2,
                                                  float* __restrict__ out, int out_size) {
    int p = blockIdx.x, tid = threadIdx.x;
    float part[Bb] = {0.f, 0.f, 0.f, 0.f};
    for (int a = tid; a < DAa; a += 128) {
        float w2 = gW2[p * DAa + a];
#pragma unroll
        for (int b = 0; b < Bb; b++) {
            float h = g_hpre[((size_t)p * Bb + b) * DAa + a];
            part[b] += gelu_exact(h) * w2;
        }
    }
    __shared__ float s_red[Bb][4];
    __shared__ float s_sc[Bb];
#pragma unroll
    for (int b = 0; b < Bb; b++) {
        float v = part[b];
#pragma unroll
        for (int o = 16; o; o >>= 1) v += __shfl_down_sync(0xffffffffu, v, o);
        if ((tid & 31) == 0) s_red[b][tid >> 5] = v;
    }
    __syncthreads();
    if (tid == 0) {
        float avg = 0.0f;
        float st[Bb];
#pragma unroll
        for (int b = 0; b < Bb; b++) {
            float d = s_red[b][0] + s_red[b][1] + s_red[b][2] + s_red[b][3] + gb2[p];
            st[b] = 1.0f / (1.0f + expf(-d));
            avg += st[b];
        }
        avg *= 0.25f;
        if (out_size >= OUT_MAIN + Pp + 1) out[OUT_MAIN + p] = avg;
        float mk = 0.0f;
        if (avg > THRESH) { mk = pg[p]; atomicAdd(&g_count, 1.0f); }
#pragma unroll
        for (int b = 0; b < Bb; b++) {
            float sc = mk * st[b];
            g_scalepb[p * Bb + b] = sc;
            s_sc[b] = sc;
        }
    }
    __syncthreads();
    float sc0 = s_sc[0], sc1 = s_sc[1], sc2 = s_sc[2], sc3 = s_sc[3];
    for (int j = tid; j < Dm; j += 128) {
        float bias = sb2[p * Dm + j];
        atomicAdd(&g_total[0 * Dm + j], sc0 * bias);
        atomicAdd(&g_total[1 * Dm + j], sc1 * bias);
        atomicAdd(&g_total[2 * Dm + j], sc2 * bias);
        atomicAdd(&g_total[3 * Dm + j], sc3 * bias);
    }
}

// ---------------- total += scale_pb * (gelu(hs) @ syn_W2) ----------------------
__global__ void __launch_bounds__(256) k_syn2(const float* __restrict__ sW2) {
    int bid = blockIdx.x;
    int ds = bid & 7;
    int p = bid >> 3;
    int tid = threadIdx.x;
    __shared__ float s_in[Bb * Dm];
#pragma unroll
    for (int k = tid; k < Bb * Dm / 4; k += 256) {
        float4 v = reinterpret_cast<const float4*>(g_hs + (size_t)p * Bb * Dm)[k];
        v.x = gelu_exact(v.x); v.y = gelu_exact(v.y);
        v.z = gelu_exact(v.z); v.w = gelu_exact(v.w);
        reinterpret_cast<float4*>(s_in)[k] = v;
    }
    __syncthreads();
    const float4* Wp = reinterpret_cast<const float4*>(sW2 + (size_t)p * Dm * Dm);
    float4 acc[Bb] = {};
    int d0 = ds * 128;
#pragma unroll 2
    for (int dd = 0; dd < 128; dd += 8) {
        float4 w[8];
#pragma unroll
        for (int j = 0; j < 8; j++) w[j] = Wp[(size_t)(d0 + dd + j) * 256 + tid];
#pragma unroll
        for (int j = 0; j < 8; j++) {
#pragma unroll
            for (int b = 0; b < Bb; b++) {
                float x = s_in[b * Dm + d0 + dd + j];
                acc[b].x += x * w[j].x; acc[b].y += x * w[j].y;
                acc[b].z += x * w[j].z; acc[b].w += x * w[j].w;
            }
        }
    }
#pragma unroll
    for (int b = 0; b < Bb; b++) {
        float sc = g_scalepb[p * Bb + b];
        float* dst = g_total + b * Dm + 4 * tid;
        atomicAdd(dst + 0, acc[b].x * sc); atomicAdd(dst + 1, acc[b].y * sc);
        atomicAdd(dst + 2, acc[b].z * sc); atomicAdd(dst + 3, acc[b].w * sc);
    }
}

// ---------------- LayerNorm(total / max(count,1)) + count aux ------------------
__global__ void __launch_bounds__(256) k_ln(const float* __restrict__ gamma,
                                            const float* __restrict__ beta,
                                            const float* __restrict__ out_b,
                                            const float* __restrict__ ag_p,
                                            float* __restrict__ out, int out_size) {
    int tid = threadIdx.x;
    __shared__ float s_red[8];
    __shared__ float s_stat;
    float inv_cnt = 1.0f / fmaxf(g_count, 1.0f);
    float ag = *ag_p;
    if (tid == 0 && out_size >= OUT_MAIN + Pp + 1) out[OUT_MAIN + Pp] = g_count;
    float4 ga = reinterpret_cast<const float4*>(gamma)[tid];
    float4 be = reinterpret_cast<const float4*>(beta)[tid];
    for (int b = 0; b < Bb; b++) {
        float4 v = reinterpret_cast<const float4*>(g_total + b * Dm)[tid];
        v.x *= inv_cnt; v.y *= inv_cnt; v.z *= inv_cnt; v.w *= inv_cnt;
        float lsum = v.x + v.y + v.z + v.w;
#pragma unroll
        for (int o = 16; o; o >>= 1) lsum += __shfl_down_sync(0xffffffffu, lsum, o);
        if ((tid & 31) == 0) s_red[tid >> 5] = lsum;
        __syncthreads();
        if (tid == 0) {
            float t = 0;
#pragma unroll
            for (int k = 0; k < 8; k++) t += s_red[k];
            s_stat = t * (1.0f / Dm);
        }
        __syncthreads();
        float mu = s_stat;
        __syncthreads();
        float dx = v.x - mu, dy = v.y - mu, dz = v.z - mu, dw = v.w - mu;
        float lsq = dx * dx + dy * dy + dz * dz + dw * dw;
#pragma unroll
        for (int o = 16; o; o >>= 1) lsq += __shfl_down_sync(0xffffffffu, lsq, o);
        if ((tid & 31) == 0) s_red[tid >> 5] = lsq;
        __syncthreads();
        if (tid == 0) {
            float t = 0;
#pragma unroll
            for (int k = 0; k < 8; k++) t += s_red[k];
            s_stat = t * (1.0f / Dm);
        }
        __syncthreads();
        float rstd = rsqrtf(s_stat + LN_EPS);
        __syncthreads();
        float4 nv;
        nv.x = dx * rstd * ga.x + be.x;
        nv.y = dy * rstd * ga.y + be.y;
        nv.z = dz * rstd * ga.z + be.z;
        nv.w = dw * rstd * ga.w + be.w;
        reinterpret_cast<float4*>(g_normed + b * Dm)[tid] = nv;
    }
    float4 ob = reinterpret_cast<const float4*>(out_b)[tid];
    ob.x *= ag; ob.y *= ag; ob.z *= ag; ob.w *= ag;
#pragma unroll
    for (int b = 0; b < Bb; b++)
        reinterpret_cast<float4*>(g_addition + b * Dm)[tid] = ob;
}

// ---------------- addition += (normed @ out_W) * gate --------------------------
__global__ void __launch_bounds__(256) k_proj(const float* __restrict__ out_W,
                                              const float* __restrict__ ag_p) {
    int ds = blockIdx.x;
    int tid = threadIdx.x;
    __shared__ float s_in[Bb * Dm];
#pragma unroll
    for (int k = tid; k < Bb * Dm / 4; k += 256)
        reinterpret_cast<float4*>(s_in)[k] = reinterpret_cast<const float4*>(g_normed)[k];
    __syncthreads();
    const float4* Wp = reinterpret_cast<const float4*>(out_W);
    float4 acc[Bb] = {};
    int d0 = ds * 32;
#pragma unroll
    for (int dd = 0; dd < 32; dd += 8) {
        float4 w[8];
#pragma unroll
        for (int j = 0; j < 8; j++) w[j] = Wp[(size_t)(d0 + dd + j) * 256 + tid];
#pragma unroll
        for (int j = 0; j < 8; j++) {
#pragma unroll
            for (int b = 0; b < Bb; b++) {
                float x = s_in[b * Dm + d0 + dd + j];
                acc[b].x += x * w[j].x; acc[b].y += x * w[j].y;
                acc[b].z += x * w[j].z; acc[b].w += x * w[j].w;
            }
        }
    }
    float ag = *ag_p;
#pragma unroll
    for (int b = 0; b < Bb; b++) {
        float* dst = g_addition + b * Dm + 4 * tid;
        atomicAdd(dst + 0, acc[b].x * ag); atomicAdd(dst + 1, acc[b].y * ag);
        atomicAdd(dst + 2, acc[b].z * ag); atomicAdd(dst + 3, acc[b].w * ag);
    }
}

// ---------------- output = bridge + addition -----------------------------------
__global__ void __launch_bounds__(256) k_output(const float* __restrict__ bridge,
                                                float* __restrict__ out) {
    size_t i4 = (size_t)blockIdx.x * 256 + threadIdx.x;
    if (i4 >= (size_t)OUT_MAIN / 4) return;
    float4 br = reinterpret_cast<const float4*>(bridge)[i4];
    int b = (int)(i4 >> 19);
    int d4 = (int)(i4 & 255);
    if (g_count > 0.0f) {
        float4 ad = reinterpret_cast<const float4*>(g_addition)[b * 256 + d4];
        br.x += ad.x; br.y += ad.y; br.z += ad.z; br.w += ad.w;
    }
    reinterpret_cast<float4*>(out)[i4] = br;
}

// ---------------- launch --------------------------------------------------------
extern "C" void kernel_launch(void* const* d_in, const int* in_sizes, int n_in,
                              void* d_out, int out_size) {
    const float* bridge = (const float*)d_in[0];
    const float* eo     = (const float*)d_in[1];
    const float* ew     = (const float*)d_in[2];
    const float* q      = (const float*)d_in[3];
    const float* Wk     = (const float*)d_in[4];
    const float* Wv     = (const float*)d_in[6];
    const float* bv     = (const float*)d_in[7];
    const float* Wa     = (const float*)d_in[8];
    const float* ba     = (const float*)d_in[9];
    const float* Wb     = (const float*)d_in[10];
    const float* bb     = (const float*)d_in[11];
    const float* gW1    = (const float*)d_in[12];
    const float* gb1    = (const float*)d_in[13];
    const float* gW2    = (const float*)d_in[14];
    const float* gb2    = (const float*)d_in[15];
    const float* sW1    = (const float*)d_in[16];
    const float* sb1    = (const float*)d_in[17];
    const float* sW2    = (const float*)d_in[18];
    const float* sb2    = (const float*)d_in[19];
    const float* pg     = (const float*)d_in[20];
    const float* gamma  = (const float*)d_in[21];
    const float* beta   = (const float*)d_in[22];
    const float* outW   = (const float*)d_in[23];
    const float* outb   = (const float*)d_in[24];
    const float* agate  = (const float*)d_in[25];
    float* out = (float*)d_out;

    int init_n = Ee * Bb * Dm + Pp * Bb * 1024 + Pp * Bb * DAa + Pp * Bb * Dm + Bb * Dm;
    k_init<<<(init_n + 255) / 256, 256>>>(bv, ba, bb, gb1, sb1);
    k_u<<<(Ee * Dm + 7) / 8, 256>>>(Wk, q);
    k_condense<<<Ee * Bb * NCHUNK, 256>>>(eo, ew);
    k_combine<<<Ee * Bb * 4, 256>>>();
    k_form<<<Ee * 32, 256>>>(Wv);
    k_pair_ab<<<Pp * 8, 256>>>(Wa, Wb);
    k_mlp1<<<Pp * 16, 256>>>(sW1, gW1);
    k_strength<<<Pp, 128>>>(gW2, gb2, pg, sb2, out, out_size);
    k_syn2<<<Pp * 8, 256>>>(sW2);
    k_ln<<<1, 256>>>(gamma, beta, outb, agate, out, out_size);
    k_proj<<<32, 256>>>(outW, agate);
    k_output<<<(OUT_MAIN / 4 + 255) / 256, 256>>>(bridge, out);
}